// round 3
// baseline (speedup 1.0000x reference)
#include <cuda_runtime.h>
#include <cuda_bf16.h>
#include <math.h>

// Problem constants
#define BB 64
#define LL 900
#define DD 64
#define TM 32          // query rows per CTA
#define TK 64          // key/value rows per tile
#define SW 960         // padded score width (15 tiles * 64)
#define QW 68          // padded Q row width
#define KW 68          // padded K/V row width
#define NTHREADS 256

// smem layout (floats):
//  S  : [TM][SW]   = 30720
//  Qs : [TM][QW]   = 2176
//  KVs: [TK][KW]   = 4352
#define S_OFF  0
#define Q_OFF  (TM * SW)
#define KV_OFF (Q_OFF + TM * QW)
#define SMEM_FLOATS (KV_OFF + TK * KW)

__global__ __launch_bounds__(NTHREADS, 1)
void sdpa_kernel(const float* __restrict__ q,
                 const float* __restrict__ k,
                 const float* __restrict__ v,
                 const int*   __restrict__ dur,
                 float* __restrict__ out,
                 float* __restrict__ score)
{
    extern __shared__ float smem[];
    float* S   = smem + S_OFF;
    float* Qs  = smem + Q_OFF;
    float* KVs = smem + KV_OFF;

    const int tile = blockIdx.x;   // 0..28
    const int b    = blockIdx.y;   // 0..63
    const int tid  = threadIdx.x;
    const int durb = dur[b];

    const int cg = tid & 31;   // col-group 0..31 -> cols cg*2, cg*2+1
    const int rg = tid >> 5;   // row-group 0..7  -> rows rg*4 .. rg*4+3
    const int r0 = rg * 4;
    const int c0 = cg * 2;

    // ---- Load Q tile (32 x 64), clamped rows for the partial last tile ----
    {
        // 512 float4 loads, 2 per thread
        #pragma unroll
        for (int it = 0; it < 2; it++) {
            int idx = tid + it * NTHREADS;        // 0..511
            int r   = idx >> 4;                   // row 0..31
            int d4  = idx & 15;                   // float4 index 0..15
            int gr  = tile * TM + r;
            if (gr > LL - 1) gr = LL - 1;         // clamp (values unused)
            float4 val = *reinterpret_cast<const float4*>(
                q + ((size_t)b * LL + gr) * DD + d4 * 4);
            *reinterpret_cast<float4*>(Qs + r * QW + d4 * 4) = val;
        }
    }

    // ================= Phase A: S = mask(QK^T / 8) =================
    for (int kt = 0; kt < 15; kt++) {
        __syncthreads();
        // load K tile (64 x 64), zero rows beyond L
        #pragma unroll
        for (int it = 0; it < 4; it++) {
            int idx = tid + it * NTHREADS;        // 0..1023
            int r   = idx >> 4;
            int d4  = idx & 15;
            int gc  = kt * TK + r;
            float4 val = make_float4(0.f, 0.f, 0.f, 0.f);
            if (gc < LL)
                val = *reinterpret_cast<const float4*>(
                    k + ((size_t)b * LL + gc) * DD + d4 * 4);
            *reinterpret_cast<float4*>(KVs + r * KW + d4 * 4) = val;
        }
        __syncthreads();

        float acc[4][2];
        #pragma unroll
        for (int i = 0; i < 4; i++) { acc[i][0] = 0.f; acc[i][1] = 0.f; }

        #pragma unroll
        for (int d4 = 0; d4 < 16; d4++) {
            float4 a0 = *reinterpret_cast<const float4*>(Qs + (r0 + 0) * QW + d4 * 4);
            float4 a1 = *reinterpret_cast<const float4*>(Qs + (r0 + 1) * QW + d4 * 4);
            float4 a2 = *reinterpret_cast<const float4*>(Qs + (r0 + 2) * QW + d4 * 4);
            float4 a3 = *reinterpret_cast<const float4*>(Qs + (r0 + 3) * QW + d4 * 4);
            float4 b0 = *reinterpret_cast<const float4*>(KVs + (c0 + 0) * KW + d4 * 4);
            float4 b1 = *reinterpret_cast<const float4*>(KVs + (c0 + 1) * KW + d4 * 4);
            acc[0][0] += a0.x*b0.x + a0.y*b0.y + a0.z*b0.z + a0.w*b0.w;
            acc[0][1] += a0.x*b1.x + a0.y*b1.y + a0.z*b1.z + a0.w*b1.w;
            acc[1][0] += a1.x*b0.x + a1.y*b0.y + a1.z*b0.z + a1.w*b0.w;
            acc[1][1] += a1.x*b1.x + a1.y*b1.y + a1.z*b1.z + a1.w*b1.w;
            acc[2][0] += a2.x*b0.x + a2.y*b0.y + a2.z*b0.z + a2.w*b0.w;
            acc[2][1] += a2.x*b1.x + a2.y*b1.y + a2.z*b1.z + a2.w*b1.w;
            acc[3][0] += a3.x*b0.x + a3.y*b0.y + a3.z*b0.z + a3.w*b0.w;
            acc[3][1] += a3.x*b1.x + a3.y*b1.y + a3.z*b1.z + a3.w*b1.w;
        }

        // mask + store to S slab (faithful: masked entries get -1e-12)
        #pragma unroll
        for (int i = 0; i < 4; i++) {
            int gr = tile * TM + r0 + i;
            bool rvalid = gr < durb;
            #pragma unroll
            for (int j = 0; j < 2; j++) {
                int c  = kt * TK + c0 + j;     // < 960
                bool valid = rvalid && (c < durb);
                S[(r0 + i) * SW + c] = valid ? acc[i][j] * 0.125f : -1e-12f;
            }
        }
    }
    __syncthreads();

    // ================= Phase B: softmax + stream score to GMEM =================
    {
        const int warp = tid >> 5;
        const int lane = tid & 31;
        #pragma unroll
        for (int qq = 0; qq < 4; qq++) {
            int row = warp * 4 + qq;
            float* Srow = S + row * SW;
            // zero the pad region (used as zeros in Phase C)
            for (int c = 900 + lane; c < SW; c += 32) Srow[c] = 0.f;
            int gr = tile * TM + row;
            if (gr < LL) {
                float m = -3.4e38f;
                for (int c = lane; c < LL; c += 32) m = fmaxf(m, Srow[c]);
                #pragma unroll
                for (int o = 16; o; o >>= 1) m = fmaxf(m, __shfl_xor_sync(0xffffffffu, m, o));
                float s = 0.f;
                for (int c = lane; c < LL; c += 32) {
                    float e = __expf(Srow[c] - m);
                    Srow[c] = e;
                    s += e;
                }
                #pragma unroll
                for (int o = 16; o; o >>= 1) s += __shfl_xor_sync(0xffffffffu, s, o);
                float inv = 1.0f / s;
                float* grow = score + ((size_t)b * LL + gr) * LL;
                for (int c = lane; c < LL; c += 32) {
                    float p = Srow[c] * inv;
                    Srow[c] = p;
                    grow[c] = p;
                }
            }
        }
    }

    // ================= Phase C: out = P @ V =================
    float o[4][2];
    #pragma unroll
    for (int i = 0; i < 4; i++) { o[i][0] = 0.f; o[i][1] = 0.f; }

    for (int vt = 0; vt < 15; vt++) {
        __syncthreads();
        #pragma unroll
        for (int it = 0; it < 4; it++) {
            int idx = tid + it * NTHREADS;
            int r   = idx >> 4;
            int d4  = idx & 15;
            int gc  = vt * TK + r;
            float4 val = make_float4(0.f, 0.f, 0.f, 0.f);
            if (gc < LL)
                val = *reinterpret_cast<const float4*>(
                    v + ((size_t)b * LL + gc) * DD + d4 * 4);
            *reinterpret_cast<float4*>(KVs + r * KW + d4 * 4) = val;
        }
        __syncthreads();

        #pragma unroll
        for (int cc = 0; cc < TK; cc += 4) {
            float4 p0 = *reinterpret_cast<const float4*>(S + (r0 + 0) * SW + vt * TK + cc);
            float4 p1 = *reinterpret_cast<const float4*>(S + (r0 + 1) * SW + vt * TK + cc);
            float4 p2 = *reinterpret_cast<const float4*>(S + (r0 + 2) * SW + vt * TK + cc);
            float4 p3 = *reinterpret_cast<const float4*>(S + (r0 + 3) * SW + vt * TK + cc);
            const float* pp0 = &p0.x;
            const float* pp1 = &p1.x;
            const float* pp2 = &p2.x;
            const float* pp3 = &p3.x;
            #pragma unroll
            for (int t = 0; t < 4; t++) {
                float v0 = KVs[(cc + t) * KW + c0 + 0];
                float v1 = KVs[(cc + t) * KW + c0 + 1];
                o[0][0] += pp0[t] * v0;  o[0][1] += pp0[t] * v1;
                o[1][0] += pp1[t] * v0;  o[1][1] += pp1[t] * v1;
                o[2][0] += pp2[t] * v0;  o[2][1] += pp2[t] * v1;
                o[3][0] += pp3[t] * v0;  o[3][1] += pp3[t] * v1;
            }
        }
    }

    // write out [B, L, D]
    #pragma unroll
    for (int i = 0; i < 4; i++) {
        int gr = tile * TM + r0 + i;
        if (gr < LL) {
            float2 val = make_float2(o[i][0], o[i][1]);
            *reinterpret_cast<float2*>(out + ((size_t)b * LL + gr) * DD + c0) = val;
        }
    }
}

extern "C" void kernel_launch(void* const* d_in, const int* in_sizes, int n_in,
                              void* d_out, int out_size)
{
    const float* q   = (const float*)d_in[0];
    const float* k   = (const float*)d_in[1];
    const float* v   = (const float*)d_in[2];
    const int*   dur = (const int*)d_in[3];

    float* out   = (float*)d_out;                       // [64,900,64]
    float* score = out + (size_t)BB * LL * DD;          // [64,900,900]

    const int smem_bytes = SMEM_FLOATS * sizeof(float); // ~149 KB
    cudaFuncSetAttribute(sdpa_kernel, cudaFuncAttributeMaxDynamicSharedMemorySize, smem_bytes);

    dim3 grid((LL + TM - 1) / TM, BB);   // (29, 64)
    sdpa_kernel<<<grid, NTHREADS, smem_bytes>>>(q, k, v, dur, out, score);
}

// round 5
// speedup vs baseline: 1.9356x; 1.9356x over previous
#include <cuda_runtime.h>
#include <cstdint>
#include <math.h>

// Problem constants
#define BB 64
#define LL 900
#define DD 64
#define TM 32          // query rows per CTA
#define TK 64          // key/value rows per tile
#define SW 964         // padded score width (960 used + pad; stride%32==4 -> conflict-free frags, 16B aligned)
#define QW 68          // Q row stride (words)
#define KW 68          // K row stride (words)
#define VW 72          // V row stride (words)
#define NTHREADS 256

// smem layout (floats):
#define S_OFF  0
#define Q_OFF  (TM * SW)                 // 30848
#define KV_OFF (Q_OFF + TM * QW)         // +2176
#define SMEM_FLOATS (KV_OFF + TK * VW)   // +4608 = 37632 floats = 150528 B

static __device__ __forceinline__ uint32_t f2tf(float f) {
    uint32_t r;
    asm("cvt.rna.tf32.f32 %0, %1;" : "=r"(r) : "f"(f));
    return r;
}

static __device__ __forceinline__ void mma_m16n8k8(float* d, const uint32_t* a,
                                                   uint32_t b0, uint32_t b1) {
    asm volatile("mma.sync.aligned.m16n8k8.row.col.f32.tf32.tf32.f32 "
                 "{%0,%1,%2,%3}, {%4,%5,%6,%7}, {%8,%9}, {%0,%1,%2,%3};"
                 : "+f"(d[0]), "+f"(d[1]), "+f"(d[2]), "+f"(d[3])
                 : "r"(a[0]), "r"(a[1]), "r"(a[2]), "r"(a[3]), "r"(b0), "r"(b1));
}

__global__ __launch_bounds__(NTHREADS, 1)
void sdpa_kernel(const float* __restrict__ q,
                 const float* __restrict__ k,
                 const float* __restrict__ v,
                 const int*   __restrict__ dur,
                 float* __restrict__ out,
                 float* __restrict__ score)
{
    extern __shared__ float smem[];
    float*    S  = smem + S_OFF;
    float*    Qs = smem + Q_OFF;
    float*    KVs= smem + KV_OFF;
    uint32_t* Su = reinterpret_cast<uint32_t*>(S);
    uint32_t* Qu = reinterpret_cast<uint32_t*>(Qs);
    uint32_t* KVu= reinterpret_cast<uint32_t*>(KVs);

    const int tile = blockIdx.x;   // 0..28
    const int b    = blockIdx.y;   // 0..63
    const int tid  = threadIdx.x;
    const int wid  = tid >> 5;
    const int lane = tid & 31;
    const int durb = dur[b];

    // warp tiling: mt in {0,1} selects rows, nc in {0..3} selects 16-col strip
    const int mt  = wid >> 2;
    const int nc  = wid & 3;
    const int grp = lane >> 2;       // 0..7
    const int qid = lane & 3;        // 0..3
    const int ar0 = mt * 16 + grp;   // A row (and +8)

    // ---- Load Q tile (32 x 64) as tf32, clamped rows for the partial last tile ----
    #pragma unroll
    for (int it = 0; it < 2; it++) {
        int idx = tid + it * NTHREADS;        // 0..511
        int r   = idx >> 4;                   // row 0..31
        int d4  = idx & 15;                   // float4 index
        int gr  = tile * TM + r;
        if (gr > LL - 1) gr = LL - 1;
        float4 val = *reinterpret_cast<const float4*>(
            q + ((size_t)b * LL + gr) * DD + d4 * 4);
        *reinterpret_cast<uint4*>(Qu + r * QW + d4 * 4) =
            make_uint4(f2tf(val.x), f2tf(val.y), f2tf(val.z), f2tf(val.w));
    }
    __syncthreads();

    // cache Q A-fragments for all 8 k-steps (reused across all 15 K-tiles)
    uint32_t qa[8][4];
    #pragma unroll
    for (int ks = 0; ks < 8; ks++) {
        qa[ks][0] = Qu[ar0 * QW + ks * 8 + qid];
        qa[ks][1] = Qu[(ar0 + 8) * QW + ks * 8 + qid];
        qa[ks][2] = Qu[ar0 * QW + ks * 8 + qid + 4];
        qa[ks][3] = Qu[(ar0 + 8) * QW + ks * 8 + qid + 4];
    }

    const bool rv0 = (tile * TM + ar0)     < durb;
    const bool rv1 = (tile * TM + ar0 + 8) < durb;

    // ================= Phase A: S = mask(QK^T / 8) via mma.sync =================
    for (int kt = 0; kt < 15; kt++) {
        // load K tile (64 keys x 64 dims) as tf32
        #pragma unroll
        for (int it = 0; it < 4; it++) {
            int idx = tid + it * NTHREADS;
            int r   = idx >> 4;
            int d4  = idx & 15;
            int gc  = kt * TK + r;
            float4 val = make_float4(0.f, 0.f, 0.f, 0.f);
            if (gc < LL)
                val = *reinterpret_cast<const float4*>(
                    k + ((size_t)b * LL + gc) * DD + d4 * 4);
            *reinterpret_cast<uint4*>(KVu + r * KW + d4 * 4) =
                make_uint4(f2tf(val.x), f2tf(val.y), f2tf(val.z), f2tf(val.w));
        }
        __syncthreads();

        float acc[2][4] = {{0.f,0.f,0.f,0.f},{0.f,0.f,0.f,0.f}};
        #pragma unroll
        for (int ks = 0; ks < 8; ks++) {
            #pragma unroll
            for (int t = 0; t < 2; t++) {
                int n0 = nc * 16 + t * 8;
                uint32_t b0 = KVu[(n0 + grp) * KW + ks * 8 + qid];
                uint32_t b1 = KVu[(n0 + grp) * KW + ks * 8 + qid + 4];
                mma_m16n8k8(acc[t], qa[ks], b0, b1);
            }
        }

        // mask + store to S slab (faithful: masked entries get -1e-12)
        #pragma unroll
        for (int t = 0; t < 2; t++) {
            int cb = kt * 64 + nc * 16 + t * 8 + qid * 2;
            #pragma unroll
            for (int e = 0; e < 2; e++) {
                int c = cb + e;
                bool cv = c < durb;
                S[ar0 * SW + c]       = (rv0 && cv) ? acc[t][e]     * 0.125f : -1e-12f;
                S[(ar0 + 8) * SW + c] = (rv1 && cv) ? acc[t][2 + e] * 0.125f : -1e-12f;
            }
        }
        __syncthreads();
    }

    // ================= Phase B: softmax + stream score to GMEM =================
    {
        #pragma unroll
        for (int qq = 0; qq < 4; qq++) {
            int row = wid * 4 + qq;
            float* Srow = S + row * SW;
            // zero the pad region (cols 900..963, used as zeros in Phase C)
            for (int c = 900 + lane; c < SW; c += 32) Srow[c] = 0.f;
            int gr = tile * TM + row;
            if (gr < LL) {
                float m = -3.4e38f;
                for (int c = lane; c < LL; c += 32) m = fmaxf(m, Srow[c]);
                #pragma unroll
                for (int o = 16; o; o >>= 1) m = fmaxf(m, __shfl_xor_sync(0xffffffffu, m, o));
                float s = 0.f;
                for (int c = lane; c < LL; c += 32) {
                    float e = __expf(Srow[c] - m);
                    Srow[c] = e;
                    s += e;
                }
                #pragma unroll
                for (int o = 16; o; o >>= 1) s += __shfl_xor_sync(0xffffffffu, s, o);
                float inv = 1.0f / s;
                float* grow = score + ((size_t)b * LL + gr) * LL;
                for (int c = lane; c < LL; c += 32) {
                    float p = Srow[c] * inv;
                    grow[c] = p;                                   // full precision to output
                    Srow[c] = __uint_as_float(f2tf(p));            // tf32 for Phase C MMA
                }
            }
        }
    }

    // ================= Phase C: out = P @ V via mma.sync =================
    float oacc[2][4] = {{0.f,0.f,0.f,0.f},{0.f,0.f,0.f,0.f}};

    for (int vt = 0; vt < 15; vt++) {
        __syncthreads();
        #pragma unroll
        for (int it = 0; it < 4; it++) {
            int idx = tid + it * NTHREADS;
            int r   = idx >> 4;
            int d4  = idx & 15;
            int gc  = vt * TK + r;
            float4 val = make_float4(0.f, 0.f, 0.f, 0.f);
            if (gc < LL)
                val = *reinterpret_cast<const float4*>(
                    v + ((size_t)b * LL + gc) * DD + d4 * 4);
            *reinterpret_cast<uint4*>(KVu + r * VW + d4 * 4) =
                make_uint4(f2tf(val.x), f2tf(val.y), f2tf(val.z), f2tf(val.w));
        }
        __syncthreads();

        #pragma unroll
        for (int ks = 0; ks < 8; ks++) {
            int kb = vt * 64 + ks * 8;
            uint32_t a[4];
            a[0] = Su[ar0 * SW + kb + qid];
            a[1] = Su[(ar0 + 8) * SW + kb + qid];
            a[2] = Su[ar0 * SW + kb + qid + 4];
            a[3] = Su[(ar0 + 8) * SW + kb + qid + 4];
            #pragma unroll
            for (int t = 0; t < 2; t++) {
                int n0 = nc * 16 + t * 8;
                uint32_t b0 = KVu[(ks * 8 + qid) * VW + n0 + grp];
                uint32_t b1 = KVu[(ks * 8 + qid + 4) * VW + n0 + grp];
                mma_m16n8k8(oacc[t], a, b0, b1);
            }
        }
    }

    // write out [B, L, D]
    {
        int gr0 = tile * TM + ar0;
        int gr1 = gr0 + 8;
        #pragma unroll
        for (int t = 0; t < 2; t++) {
            int c = nc * 16 + t * 8 + qid * 2;
            if (gr0 < LL)
                *reinterpret_cast<float2*>(out + ((size_t)b * LL + gr0) * DD + c) =
                    make_float2(oacc[t][0], oacc[t][1]);
            if (gr1 < LL)
                *reinterpret_cast<float2*>(out + ((size_t)b * LL + gr1) * DD + c) =
                    make_float2(oacc[t][2], oacc[t][3]);
        }
    }
}

extern "C" void kernel_launch(void* const* d_in, const int* in_sizes, int n_in,
                              void* d_out, int out_size)
{
    const float* q   = (const float*)d_in[0];
    const float* k   = (const float*)d_in[1];
    const float* v   = (const float*)d_in[2];
    const int*   dur = (const int*)d_in[3];

    float* out   = (float*)d_out;                       // [64,900,64]
    float* score = out + (size_t)BB * LL * DD;          // [64,900,900]

    const int smem_bytes = SMEM_FLOATS * sizeof(float); // ~147 KB
    cudaFuncSetAttribute(sdpa_kernel, cudaFuncAttributeMaxDynamicSharedMemorySize, smem_bytes);

    dim3 grid((LL + TM - 1) / TM, BB);   // (29, 64)
    sdpa_kernel<<<grid, NTHREADS, smem_bytes>>>(q, k, v, dur, out, score);
}

// round 6
// speedup vs baseline: 1.9413x; 1.0030x over previous
#include <cuda_runtime.h>
#include <cstdint>
#include <math.h>

// Problem constants
#define BB 64
#define LL 900
#define DD 64
#define TM 32          // query rows per CTA
#define TK 64          // key/value rows per tile
#define SW 964         // padded score width (960 used + pad; stride%32==4 -> conflict-free frags, 16B aligned)
#define QW 68          // Q row stride (words)
#define KW 68          // K row stride (words)
#define VW 72          // V row stride (words)
#define NTHREADS 256

// smem layout (floats):
#define S_OFF  0
#define Q_OFF  (TM * SW)                 // 30848
#define KV_OFF (Q_OFF + TM * QW)         // +2176
#define SMEM_FLOATS (KV_OFF + TK * VW)   // +4608 = 37632 floats = 150528 B

static __device__ __forceinline__ uint32_t f2tf(float f) {
    uint32_t r;
    asm("cvt.rna.tf32.f32 %0, %1;" : "=r"(r) : "f"(f));
    return r;
}

static __device__ __forceinline__ void mma_m16n8k8(float* d, const uint32_t* a,
                                                   uint32_t b0, uint32_t b1) {
    asm volatile("mma.sync.aligned.m16n8k8.row.col.f32.tf32.tf32.f32 "
                 "{%0,%1,%2,%3}, {%4,%5,%6,%7}, {%8,%9}, {%0,%1,%2,%3};"
                 : "+f"(d[0]), "+f"(d[1]), "+f"(d[2]), "+f"(d[3])
                 : "r"(a[0]), "r"(a[1]), "r"(a[2]), "r"(a[3]), "r"(b0), "r"(b1));
}

__global__ __launch_bounds__(NTHREADS, 1)
void sdpa_kernel(const float* __restrict__ q,
                 const float* __restrict__ k,
                 const float* __restrict__ v,
                 const int*   __restrict__ dur,
                 float* __restrict__ out,
                 float* __restrict__ score)
{
    extern __shared__ float smem[];
    float*    S  = smem + S_OFF;
    float*    Qs = smem + Q_OFF;
    float*    KVs= smem + KV_OFF;
    uint32_t* Su = reinterpret_cast<uint32_t*>(S);
    uint32_t* Qu = reinterpret_cast<uint32_t*>(Qs);
    uint32_t* KVu= reinterpret_cast<uint32_t*>(KVs);

    const int tile = blockIdx.x;   // 0..28
    const int b    = blockIdx.y;   // 0..63
    const int tid  = threadIdx.x;
    const int wid  = tid >> 5;
    const int lane = tid & 31;
    const int durb = dur[b];

    // warp tiling: mt in {0,1} selects rows, nc in {0..3} selects 16-col strip
    const int mt  = wid >> 2;
    const int nc  = wid & 3;
    const int grp = lane >> 2;       // 0..7
    const int qid = lane & 3;        // 0..3
    const int ar0 = mt * 16 + grp;   // A row (and +8)

    // ---- Load Q tile (32 x 64) as tf32, clamped rows for the partial last tile ----
    #pragma unroll
    for (int it = 0; it < 2; it++) {
        int idx = tid + it * NTHREADS;        // 0..511
        int r   = idx >> 4;                   // row 0..31
        int d4  = idx & 15;                   // float4 index
        int gr  = tile * TM + r;
        if (gr > LL - 1) gr = LL - 1;
        float4 val = *reinterpret_cast<const float4*>(
            q + ((size_t)b * LL + gr) * DD + d4 * 4);
        *reinterpret_cast<uint4*>(Qu + r * QW + d4 * 4) =
            make_uint4(f2tf(val.x), f2tf(val.y), f2tf(val.z), f2tf(val.w));
    }
    __syncthreads();

    // cache Q A-fragments for all 8 k-steps (reused across all 15 K-tiles)
    uint32_t qa[8][4];
    #pragma unroll
    for (int ks = 0; ks < 8; ks++) {
        qa[ks][0] = Qu[ar0 * QW + ks * 8 + qid];
        qa[ks][1] = Qu[(ar0 + 8) * QW + ks * 8 + qid];
        qa[ks][2] = Qu[ar0 * QW + ks * 8 + qid + 4];
        qa[ks][3] = Qu[(ar0 + 8) * QW + ks * 8 + qid + 4];
    }

    const bool rv0 = (tile * TM + ar0)     < durb;
    const bool rv1 = (tile * TM + ar0 + 8) < durb;

    // ================= Phase A: S = mask(QK^T / 8) via mma.sync =================
    for (int kt = 0; kt < 15; kt++) {
        // load K tile (64 keys x 64 dims) as tf32
        #pragma unroll
        for (int it = 0; it < 4; it++) {
            int idx = tid + it * NTHREADS;
            int r   = idx >> 4;
            int d4  = idx & 15;
            int gc  = kt * TK + r;
            float4 val = make_float4(0.f, 0.f, 0.f, 0.f);
            if (gc < LL)
                val = *reinterpret_cast<const float4*>(
                    k + ((size_t)b * LL + gc) * DD + d4 * 4);
            *reinterpret_cast<uint4*>(KVu + r * KW + d4 * 4) =
                make_uint4(f2tf(val.x), f2tf(val.y), f2tf(val.z), f2tf(val.w));
        }
        __syncthreads();

        float acc[2][4] = {{0.f,0.f,0.f,0.f},{0.f,0.f,0.f,0.f}};
        #pragma unroll
        for (int ks = 0; ks < 8; ks++) {
            #pragma unroll
            for (int t = 0; t < 2; t++) {
                int n0 = nc * 16 + t * 8;
                uint32_t b0 = KVu[(n0 + grp) * KW + ks * 8 + qid];
                uint32_t b1 = KVu[(n0 + grp) * KW + ks * 8 + qid + 4];
                mma_m16n8k8(acc[t], qa[ks], b0, b1);
            }
        }

        // mask + store to S slab (faithful: masked entries get -1e-12)
        #pragma unroll
        for (int t = 0; t < 2; t++) {
            int cb = kt * 64 + nc * 16 + t * 8 + qid * 2;
            #pragma unroll
            for (int e = 0; e < 2; e++) {
                int c = cb + e;
                bool cv = c < durb;
                S[ar0 * SW + c]       = (rv0 && cv) ? acc[t][e]     * 0.125f : -1e-12f;
                S[(ar0 + 8) * SW + c] = (rv1 && cv) ? acc[t][2 + e] * 0.125f : -1e-12f;
            }
        }
        __syncthreads();
    }

    // ================= Phase B: softmax + stream score to GMEM =================
    {
        #pragma unroll
        for (int qq = 0; qq < 4; qq++) {
            int row = wid * 4 + qq;
            float* Srow = S + row * SW;
            // zero the pad region (cols 900..963, used as zeros in Phase C)
            for (int c = 900 + lane; c < SW; c += 32) Srow[c] = 0.f;
            int gr = tile * TM + row;
            if (gr < LL) {
                float m = -3.4e38f;
                for (int c = lane; c < LL; c += 32) m = fmaxf(m, Srow[c]);
                #pragma unroll
                for (int o = 16; o; o >>= 1) m = fmaxf(m, __shfl_xor_sync(0xffffffffu, m, o));
                float s = 0.f;
                for (int c = lane; c < LL; c += 32) {
                    float e = __expf(Srow[c] - m);
                    Srow[c] = e;
                    s += e;
                }
                #pragma unroll
                for (int o = 16; o; o >>= 1) s += __shfl_xor_sync(0xffffffffu, s, o);
                float inv = 1.0f / s;
                float* grow = score + ((size_t)b * LL + gr) * LL;
                for (int c = lane; c < LL; c += 32) {
                    float p = Srow[c] * inv;
                    grow[c] = p;                                   // full precision to output
                    Srow[c] = __uint_as_float(f2tf(p));            // tf32 for Phase C MMA
                }
            }
        }
    }

    // ================= Phase C: out = P @ V via mma.sync =================
    float oacc[2][4] = {{0.f,0.f,0.f,0.f},{0.f,0.f,0.f,0.f}};

    for (int vt = 0; vt < 15; vt++) {
        __syncthreads();
        #pragma unroll
        for (int it = 0; it < 4; it++) {
            int idx = tid + it * NTHREADS;
            int r   = idx >> 4;
            int d4  = idx & 15;
            int gc  = vt * TK + r;
            float4 val = make_float4(0.f, 0.f, 0.f, 0.f);
            if (gc < LL)
                val = *reinterpret_cast<const float4*>(
                    v + ((size_t)b * LL + gc) * DD + d4 * 4);
            *reinterpret_cast<uint4*>(KVu + r * VW + d4 * 4) =
                make_uint4(f2tf(val.x), f2tf(val.y), f2tf(val.z), f2tf(val.w));
        }
        __syncthreads();

        #pragma unroll
        for (int ks = 0; ks < 8; ks++) {
            int kb = vt * 64 + ks * 8;
            uint32_t a[4];
            a[0] = Su[ar0 * SW + kb + qid];
            a[1] = Su[(ar0 + 8) * SW + kb + qid];
            a[2] = Su[ar0 * SW + kb + qid + 4];
            a[3] = Su[(ar0 + 8) * SW + kb + qid + 4];
            #pragma unroll
            for (int t = 0; t < 2; t++) {
                int n0 = nc * 16 + t * 8;
                uint32_t b0 = KVu[(ks * 8 + qid) * VW + n0 + grp];
                uint32_t b1 = KVu[(ks * 8 + qid + 4) * VW + n0 + grp];
                mma_m16n8k8(oacc[t], a, b0, b1);
            }
        }
    }

    // write out [B, L, D]
    {
        int gr0 = tile * TM + ar0;
        int gr1 = gr0 + 8;
        #pragma unroll
        for (int t = 0; t < 2; t++) {
            int c = nc * 16 + t * 8 + qid * 2;
            if (gr0 < LL)
                *reinterpret_cast<float2*>(out + ((size_t)b * LL + gr0) * DD + c) =
                    make_float2(oacc[t][0], oacc[t][1]);
            if (gr1 < LL)
                *reinterpret_cast<float2*>(out + ((size_t)b * LL + gr1) * DD + c) =
                    make_float2(oacc[t][2], oacc[t][3]);
        }
    }
}

extern "C" void kernel_launch(void* const* d_in, const int* in_sizes, int n_in,
                              void* d_out, int out_size)
{
    const float* q   = (const float*)d_in[0];
    const float* k   = (const float*)d_in[1];
    const float* v   = (const float*)d_in[2];
    const int*   dur = (const int*)d_in[3];

    float* out   = (float*)d_out;                       // [64,900,64]
    float* score = out + (size_t)BB * LL * DD;          // [64,900,900]

    const int smem_bytes = SMEM_FLOATS * sizeof(float); // ~147 KB
    cudaFuncSetAttribute(sdpa_kernel, cudaFuncAttributeMaxDynamicSharedMemorySize, smem_bytes);

    dim3 grid((LL + TM - 1) / TM, BB);   // (29, 64)
    sdpa_kernel<<<grid, NTHREADS, smem_bytes>>>(q, k, v, dur, out, score);
}